// round 16
// baseline (speedup 1.0000x reference)
#include <cuda_runtime.h>
#include <math.h>

#define PS 16
#define NB 32
#define IMGSZ (1024*1024)
#define S2 149                    // per-batch partial stride (21 mod 32)
#define POFF 80                   // patch-1 offset (16 mod 32) within a batch

__device__ __forceinline__ float clamp01(float x) {
    return fminf(fmaxf(x, 0.0f), 1.0f);
}

// ---------------------------------------------------------------------------
// One CTA = one PATCH-PAIR, all 32 batches, 512 threads.
// t: c8 = t&7 (16B chunk across the 128B pair row), slot = t>>3,
// r = slot&15, s4 = slot>>4. v[8] float4 = batches 4k+s4 (32 regs).
// Every warp touches 128B-contiguous rows (vs 64B in the 1-patch design)
// -> half the DRAM row activations per byte.
//  stats: per-(b,patch) partials in bank-engineered smem; 64-thread serial
//         finalize (2 warps); 2 warps compute the 2 patch codes in parallel.
//  apply: CTA-uniform-by-construction barriers; affine from registers with
//         STG.128 streaming stores; blur via `anyblur` staged path.
// ---------------------------------------------------------------------------
__global__ void __launch_bounds__(512, 2)
fused_kernel(const float* __restrict__ img,
             const float* __restrict__ noise,
             const float* __restrict__ r_strong,
             const float* __restrict__ r_drop,
             const float* __restrict__ r_else,
             const float* __restrict__ bright_f,
             const float* __restrict__ contrast_f,
             const float* __restrict__ slight_f,
             const int*   __restrict__ aug_choice,
             const int*   __restrict__ slight_choice,
             float* __restrict__ out) {
    // union: [0..4768) psA, [4768..9536) psB   (stats partials)
    //        [0..9216) blur tile [16][16][36]  (blur halves)
    __shared__ float ubuf[9536];
    __shared__ float s_q[64], s_m[64];       // [patch*32 + b]
    __shared__ int   s_codes[2];
    __shared__ float s_als[2], s_bes[2], s_des[2];

    const int u    = blockIdx.x;             // pair id 0..2047
    const int sy   = u >> 5;
    const int pr   = u & 31;                 // pair col 0..31
    const int t    = threadIdx.x;
    const int c8   = t & 7;                  // 16B chunk across pair
    const int slot = t >> 3;                 // 0..63
    const int r    = slot & 15;
    const int s4   = slot >> 4;              // batch phase 0..3
    const int patch = c8 >> 2;               // 0..1
    const int c8p   = c8 & 3;                // chunk within patch

    const int gofs = (sy * PS + r) * 1024 + pr * 32 + c8 * 4;

    // ---- Phase 1: 8 front-batched LDG.128 (batches 4k+s4) ----
    float4 v[8];
#pragma unroll
    for (int k = 0; k < 8; ++k)
        v[k] = *reinterpret_cast<const float4*>(
                   img + (size_t)(4 * k + s4) * IMGSZ + gofs);

    // ---- Phase 2a: in-register partials -> smem (conflict-free STS) ----
    float* psA = ubuf;
    float* psB = ubuf + 32 * S2;             // 4768
#pragma unroll
    for (int k = 0; k < 8; ++k) {
        const int b = 4 * k + s4;
        float s  = (v[k].x + v[k].y) + (v[k].z + v[k].w);
        float ss = fmaf(v[k].x, v[k].x,
                   fmaf(v[k].y, v[k].y,
                   fmaf(v[k].z, v[k].z, v[k].w * v[k].w)));
        const int idx = b * S2 + POFF * patch + r * 4 + c8p;
        psA[idx] = s;
        psB[idx] = ss;
    }
    __syncthreads();

    // ---- Phase 2b: finalize. 64 threads (2 warps), unit = (b, patch) ----
    if (t < 64) {
        const int b  = t >> 1;
        const int pa = t & 1;
        const int base = b * S2 + POFF * pa;
        float s = 0.f, ss = 0.f;
#pragma unroll
        for (int j = 0; j < 64; ++j) {
            s  += psA[base + j];
            ss += psB[base + j];
        }
        float mean = s * (1.0f / 256.0f);
        float var  = (ss - s * s * (1.0f / 256.0f)) * (1.0f / 255.0f); // ddof=1
        var = fmaxf(var, 0.0f);
        float std_ = sqrtf(var);
        float iq   = 1.0f - 2.0f * fabsf(mean - 0.5f);
        s_q[pa * 32 + b] = (std_ + iq + var) * (1.0f / 3.0f);
        s_m[pa * 32 + b] = mean;
    }
    __syncthreads();

    // ---- Phase 3: warp 0 -> patch 0 code, warp 1 -> patch 1 code ----
    if (t < 64) {
        const int pa   = t >> 5;
        const int lane = t & 31;
        float q = s_q[pa * 32 + lane];
        float m = s_m[pa * 32 + lane];
#pragma unroll
        for (int off = 16; off >= 1; off >>= 1) {
            q += __shfl_down_sync(0xffffffffu, q, off);
            m += __shfl_down_sync(0xffffffffu, m, off);
        }
        if (lane == 0) {
            q *= (1.0f / NB);
            m *= (1.0f / NB);
            const int pg = sy * 64 + pr * 2 + pa;

            bool low    = q < 0.7f;
            bool strong = low  && (r_strong[pg] < 0.8f);
            bool drop   = low  && (q < 0.3f) && (r_drop[pg] < 0.1f);
            bool els    = !low && (r_else[pg] < 0.3f);

            int code = 0;
            if (strong) code = aug_choice[pg] + 1;      // 1..4
            if (els)    code = slight_choice[pg] + 5;   // 5..6
            if (drop)   code = 7;

            float alpha = 1.f, beta = 0.f, delta = 0.f;
            if      (code == 1) beta = 0.1f;
            else if (code == 3) alpha = bright_f[pg];
            else if (code == 4) { float cf = contrast_f[pg]; alpha = cf; delta = m * (1.0f - cf); }
            else if (code == 5) beta = 0.05f;
            else if (code == 6) alpha = slight_f[pg];
            else if (code == 7) alpha = 0.f;

            s_codes[pa] = code;
            s_als[pa] = alpha; s_bes[pa] = beta; s_des[pa] = delta;
        }
    }
    __syncthreads();

    const int   code = s_codes[patch];       // uniform per half-warp
    const float al   = s_als[patch];
    const float be   = s_bes[patch];
    const float de   = s_des[patch];
    const bool  anyblur = (s_codes[0] == 2) || (s_codes[1] == 2);  // CTA-uniform

    // ---- Phase 4: apply + STG.128 streaming stores ----
    if (!anyblur) {
        if (be != 0.0f) {
#pragma unroll
            for (int k0 = 0; k0 < 8; k0 += 4) {
                float4 n[4];
#pragma unroll
                for (int kk = 0; kk < 4; ++kk)
                    n[kk] = *reinterpret_cast<const float4*>(
                                noise + (size_t)(4 * (k0 + kk) + s4) * IMGSZ + gofs);
#pragma unroll
                for (int kk = 0; kk < 4; ++kk) {
                    const int k = k0 + kk;
                    float4 o;
                    o.x = clamp01(fmaf(be, n[kk].x, fmaf(al, v[k].x, de)));
                    o.y = clamp01(fmaf(be, n[kk].y, fmaf(al, v[k].y, de)));
                    o.z = clamp01(fmaf(be, n[kk].z, fmaf(al, v[k].z, de)));
                    o.w = clamp01(fmaf(be, n[kk].w, fmaf(al, v[k].w, de)));
                    __stcs(reinterpret_cast<float4*>(
                               out + (size_t)(4 * k + s4) * IMGSZ + gofs), o);
                }
            }
        } else {
#pragma unroll
            for (int k = 0; k < 8; ++k) {
                float4 o;
                o.x = clamp01(fmaf(al, v[k].x, de));
                o.y = clamp01(fmaf(al, v[k].y, de));
                o.z = clamp01(fmaf(al, v[k].z, de));
                o.w = clamp01(fmaf(al, v[k].w, de));
                __stcs(reinterpret_cast<float4*>(
                           out + (size_t)(4 * k + s4) * IMGSZ + gofs), o);
            }
        }
    } else {
        // staged path: 16 batches per half through the union buffer.
        // Barriers are CTA-uniform; lanes diverge only between store flavors.
#pragma unroll
        for (int h = 0; h < 2; ++h) {
            __syncthreads();                 // partials / previous half done
#pragma unroll
            for (int k = 4 * h; k < 4 * h + 4; ++k) {
                const int bl = (4 * k + s4) - 16 * h;   // 0..15
                *reinterpret_cast<float4*>(
                    ubuf + bl * 576 + r * 36 + c8 * 4) = v[k];
            }
            __syncthreads();
#pragma unroll
            for (int k = 4 * h; k < 4 * h + 4; ++k) {
                const int bl = (4 * k + s4) - 16 * h;
                float4 o;
                if (code == 2) {
                    const float* tb = ubuf + bl * 576;
                    float rs[4];
#pragma unroll
                    for (int j = 0; j < 4; ++j) {
                        const int tc = c8 * 4 + j;      // col in pair 0..31
                        const int lc = tc & 15;         // col in patch
                        float sum = 0.f;
#pragma unroll
                        for (int dy = -1; dy <= 1; ++dy) {
                            const int rr = r + dy;
                            if (rr < 0 || rr >= PS) continue;
#pragma unroll
                            for (int dx = -1; dx <= 1; ++dx) {
                                const int cc = lc + dx;
                                if (cc < 0 || cc >= PS) continue;
                                sum += tb[rr * 36 + tc + dx];
                            }
                        }
                        rs[j] = sum * (1.0f / 9.0f);
                    }
                    o = make_float4(rs[0], rs[1], rs[2], rs[3]);
                } else if (be != 0.0f) {
                    float4 n = *reinterpret_cast<const float4*>(
                                   noise + (size_t)(4 * k + s4) * IMGSZ + gofs);
                    o.x = clamp01(fmaf(be, n.x, fmaf(al, v[k].x, de)));
                    o.y = clamp01(fmaf(be, n.y, fmaf(al, v[k].y, de)));
                    o.z = clamp01(fmaf(be, n.z, fmaf(al, v[k].z, de)));
                    o.w = clamp01(fmaf(be, n.w, fmaf(al, v[k].w, de)));
                } else {
                    o.x = clamp01(fmaf(al, v[k].x, de));
                    o.y = clamp01(fmaf(al, v[k].y, de));
                    o.z = clamp01(fmaf(al, v[k].z, de));
                    o.w = clamp01(fmaf(al, v[k].w, de));
                }
                __stcs(reinterpret_cast<float4*>(
                           out + (size_t)(4 * k + s4) * IMGSZ + gofs), o);
            }
        }
    }
}

extern "C" void kernel_launch(void* const* d_in, const int* in_sizes, int n_in,
                              void* d_out, int out_size) {
    const float* img           = (const float*)d_in[0];
    const float* noise         = (const float*)d_in[1];
    const float* r_strong      = (const float*)d_in[2];
    const float* r_drop        = (const float*)d_in[3];
    const float* r_else        = (const float*)d_in[4];
    const float* bright_f      = (const float*)d_in[5];
    const float* contrast_f    = (const float*)d_in[6];
    const float* slight_f      = (const float*)d_in[7];
    const int*   aug_choice    = (const int*)d_in[8];
    const int*   slight_choice = (const int*)d_in[9];
    float* out = (float*)d_out;

    fused_kernel<<<2048, 512>>>(img, noise, r_strong, r_drop, r_else,
                                bright_f, contrast_f, slight_f,
                                aug_choice, slight_choice, out);
}